// round 1
// baseline (speedup 1.0000x reference)
#include <cuda_runtime.h>
#include <cstdint>
#include <cstddef>

namespace {

constexpr int kB  = 4;
constexpr int kH  = 8;
constexpr int kL  = 2048;
constexpr int kR  = 8;
constexpr int kDV = 128;

constexpr int TM = 128;   // rows per CTA
constexpr int TN = 64;    // column tile for pass 2
constexpr int NT = 256;   // threads per CTA
constexpr int PAD_TM = TM + 4;  // 132: 16B-aligned row stride for p[j][i]

typedef unsigned long long ull;

__device__ __forceinline__ ull dup2(float x) {
    ull r; asm("mov.b64 %0, {%1,%1};" : "=l"(r) : "f"(x)); return r;
}
__device__ __forceinline__ void unpack2(ull v, float& lo, float& hi) {
    asm("mov.b64 {%0,%1}, %2;" : "=f"(lo), "=f"(hi) : "l"(v));
}
__device__ __forceinline__ ull fma2(ull a, ull b, ull c) {
    ull d; asm("fma.rn.f32x2 %0, %1, %2, %3;" : "=l"(d) : "l"(a), "l"(b), "l"(c));
    return d;
}

struct SmemLayout {
    float a2[kR][kL];      // 64 KB: full a2 slab for this (b,h)
    float a1t[kR][TM];     // 4 KB: a1 row-tile, transposed [r][i]
    float inv[TM];         // 512 B: 1/rowsum
    float p[TN][PAD_TM];   // 33 KB: prob tile, transposed [j][i]
    float v[TN][kDV];      // 32 KB: v tile [j][d]
};
// total = 136704 bytes

__global__ void __launch_bounds__(NT, 1)
fra_kernel(const float* __restrict__ gv,
           const float* __restrict__ ga1,
           const float* __restrict__ ga2,
           const int*   __restrict__ gmask,
           float* __restrict__ gout,
           float* __restrict__ gattn)
{
    extern __shared__ char smem_raw[];
    SmemLayout& S = *reinterpret_cast<SmemLayout*>(smem_raw);

    const int h    = blockIdx.x;   // heads fastest: 8 heads share one mask row-tile in L2
    const int tile = blockIdx.y;
    const int b    = blockIdx.z;
    const int bh   = b * kH + h;
    const int i0g  = tile * TM;
    const int t    = threadIdx.x;

    const float* a2base  = ga2 + (size_t)bh * kR * kL;
    const float* a1base  = ga1 + ((size_t)bh * kL + i0g) * kR;
    const float* vbase   = gv  + (size_t)bh * kL * kDV;
    const int*   mbase   = gmask + ((size_t)b * kL + i0g) * kL;
    float* attnbase      = gattn + ((size_t)bh * kL + i0g) * kL;
    float* outbase       = gout  + ((size_t)bh * kL + i0g) * kDV;

    // ---- load a2 (R x L) into smem ----
    {
        const float4* src = reinterpret_cast<const float4*>(a2base);
        float4* dst = reinterpret_cast<float4*>(&S.a2[0][0]);
        #pragma unroll
        for (int k = 0; k < (kR * kL / 4) / NT; ++k)
            dst[t + k * NT] = src[t + k * NT];
    }
    // ---- load a1 tile transposed ----
    if (t < TM) {
        const float4* src = reinterpret_cast<const float4*>(a1base + (size_t)t * kR);
        float4 q0 = src[0];
        float4 q1 = src[1];
        S.a1t[0][t] = q0.x; S.a1t[1][t] = q0.y; S.a1t[2][t] = q0.z; S.a1t[3][t] = q0.w;
        S.a1t[4][t] = q1.x; S.a1t[5][t] = q1.y; S.a1t[6][t] = q1.z; S.a1t[7][t] = q1.w;
    }
    __syncthreads();

    // ================= Phase 1: rowsum of exp(masked scores) =================
    // 2 threads per row; each scans 1024 columns. No max-subtraction: |s|<~25,
    // exp(s) cannot overflow fp32; masked entries contribute exact 0 (ref: exp(-1e9)=0).
    {
        const int i = t >> 1;
        const int jstart = (t & 1) * (kL / 2);
        ull a1d[kR];
        #pragma unroll
        for (int r = 0; r < kR; ++r) a1d[r] = dup2(S.a1t[r][i]);

        const int* mrow = mbase + (size_t)i * kL + jstart;
        const float* a2row0 = &S.a2[0][jstart];

        float s0 = 0.f, s1 = 0.f, s2 = 0.f, s3 = 0.f;
        #pragma unroll 4
        for (int j = 0; j < kL / 2; j += 4) {
            int4 m = *reinterpret_cast<const int4*>(mrow + j);
            ull acc01 = 0ULL, acc23 = 0ULL;
            #pragma unroll
            for (int r = 0; r < kR; ++r) {
                ulonglong2 a2q = *reinterpret_cast<const ulonglong2*>(a2row0 + (size_t)r * kL + j);
                acc01 = fma2(a1d[r], a2q.x, acc01);
                acc23 = fma2(a1d[r], a2q.y, acc23);
            }
            float e0, e1, e2, e3;
            unpack2(acc01, e0, e1);
            unpack2(acc23, e2, e3);
            s0 += __expf(e0) * (float)m.x;
            s1 += __expf(e1) * (float)m.y;
            s2 += __expf(e2) * (float)m.z;
            s3 += __expf(e3) * (float)m.w;
        }
        float sum = (s0 + s1) + (s2 + s3);
        sum += __shfl_xor_sync(0xffffffffu, sum, 1);
        if ((t & 1) == 0) S.inv[i] = 1.0f / sum;
    }
    __syncthreads();

    // ================= Phase 2: per column-tile, probs + PV GEMM =================
    // score-phase mapping: thread -> rows {t>>2, (t>>2)+64}, 16 cols starting (t&3)*16
    const int sa_i0 = t >> 2;
    const int sa_i1 = sa_i0 + 64;
    const int sa_c0 = (t & 3) * 16;

    // GEMM mapping: 16x16 thread grid, 8x8 microtile (4 packed f32x2 per row)
    const int ty8 = (t >> 4) * 8;
    const int tx8 = (t & 15) * 8;

    ull acc[8][4];
    #pragma unroll
    for (int r = 0; r < 8; ++r)
        #pragma unroll
        for (int c = 0; c < 4; ++c) acc[r][c] = 0ULL;

    for (int jt = 0; jt < kL / TN; ++jt) {
        const int j0 = jt * TN;

        // ---- (a) compute prob tile, write attn (global) + p (smem, transposed) ----
        {
            ull a1dA[kR], a1dB[kR];
            #pragma unroll
            for (int r = 0; r < kR; ++r) {
                a1dA[r] = dup2(S.a1t[r][sa_i0]);
                a1dB[r] = dup2(S.a1t[r][sa_i1]);
            }
            const float invA = S.inv[sa_i0];
            const float invB = S.inv[sa_i1];
            const int* mrA = mbase + (size_t)sa_i0 * kL + j0 + sa_c0;
            const int* mrB = mbase + (size_t)sa_i1 * kL + j0 + sa_c0;
            float* atA = attnbase + (size_t)sa_i0 * kL + j0 + sa_c0;
            float* atB = attnbase + (size_t)sa_i1 * kL + j0 + sa_c0;

            #pragma unroll
            for (int g = 0; g < 4; ++g) {
                const int jj = sa_c0 + g * 4;   // column within tile
                ull sA01 = 0ULL, sA23 = 0ULL, sB01 = 0ULL, sB23 = 0ULL;
                #pragma unroll
                for (int r = 0; r < kR; ++r) {
                    ulonglong2 a2q =
                        *reinterpret_cast<const ulonglong2*>(&S.a2[r][j0 + jj]);
                    sA01 = fma2(a1dA[r], a2q.x, sA01);
                    sA23 = fma2(a1dA[r], a2q.y, sA23);
                    sB01 = fma2(a1dB[r], a2q.x, sB01);
                    sB23 = fma2(a1dB[r], a2q.y, sB23);
                }
                int4 mA = *reinterpret_cast<const int4*>(mrA + g * 4);
                int4 mB = *reinterpret_cast<const int4*>(mrB + g * 4);

                float f0, f1, f2, f3;
                unpack2(sA01, f0, f1); unpack2(sA23, f2, f3);
                float4 pA;
                pA.x = __expf(f0) * invA * (float)mA.x;
                pA.y = __expf(f1) * invA * (float)mA.y;
                pA.z = __expf(f2) * invA * (float)mA.z;
                pA.w = __expf(f3) * invA * (float)mA.w;

                unpack2(sB01, f0, f1); unpack2(sB23, f2, f3);
                float4 pB;
                pB.x = __expf(f0) * invB * (float)mB.x;
                pB.y = __expf(f1) * invB * (float)mB.y;
                pB.z = __expf(f2) * invB * (float)mB.z;
                pB.w = __expf(f3) * invB * (float)mB.w;

                *reinterpret_cast<float4*>(atA + g * 4) = pA;
                *reinterpret_cast<float4*>(atB + g * 4) = pB;

                S.p[jj + 0][sa_i0] = pA.x;
                S.p[jj + 1][sa_i0] = pA.y;
                S.p[jj + 2][sa_i0] = pA.z;
                S.p[jj + 3][sa_i0] = pA.w;
                S.p[jj + 0][sa_i1] = pB.x;
                S.p[jj + 1][sa_i1] = pB.y;
                S.p[jj + 2][sa_i1] = pB.z;
                S.p[jj + 3][sa_i1] = pB.w;
            }
        }

        // ---- (b) load v tile [TN][DV] ----
        {
            const float4* vsrc = reinterpret_cast<const float4*>(vbase + (size_t)j0 * kDV);
            float4* vdst = reinterpret_cast<float4*>(&S.v[0][0]);
            #pragma unroll
            for (int k = 0; k < (TN * kDV / 4) / NT; ++k)   // 8 iters
                vdst[t + k * NT] = vsrc[t + k * NT];
        }
        __syncthreads();

        // ---- (c) GEMM: acc[i][d] += p[j][i] * v[j][d], packed f32x2 over d ----
        #pragma unroll 2
        for (int jj = 0; jj < TN; ++jj) {
            float4 pa = *reinterpret_cast<const float4*>(&S.p[jj][ty8]);
            float4 pb = *reinterpret_cast<const float4*>(&S.p[jj][ty8 + 4]);
            ulonglong2 va = *reinterpret_cast<const ulonglong2*>(&S.v[jj][tx8]);
            ulonglong2 vb = *reinterpret_cast<const ulonglong2*>(&S.v[jj][tx8 + 4]);
            #pragma unroll
            for (int r = 0; r < 8; ++r) {
                float pr = (r < 4) ? (&pa.x)[r] : (&pb.x)[r - 4];
                ull pd = dup2(pr);
                acc[r][0] = fma2(pd, va.x, acc[r][0]);
                acc[r][1] = fma2(pd, va.y, acc[r][1]);
                acc[r][2] = fma2(pd, vb.x, acc[r][2]);
                acc[r][3] = fma2(pd, vb.y, acc[r][3]);
            }
        }
        __syncthreads();
    }

    // ---- epilogue: write out tile ----
    #pragma unroll
    for (int r = 0; r < 8; ++r) {
        const int i = ty8 + r;
        float4 o0, o1;
        unpack2(acc[r][0], o0.x, o0.y);
        unpack2(acc[r][1], o0.z, o0.w);
        unpack2(acc[r][2], o1.x, o1.y);
        unpack2(acc[r][3], o1.z, o1.w);
        float4* dst = reinterpret_cast<float4*>(outbase + (size_t)i * kDV + tx8);
        dst[0] = o0;
        dst[1] = o1;
    }
}

} // namespace

extern "C" void kernel_launch(void* const* d_in, const int* in_sizes, int n_in,
                              void* d_out, int out_size) {
    const float* v    = (const float*)d_in[0];
    const float* a1   = (const float*)d_in[1];
    const float* a2   = (const float*)d_in[2];
    const int*   mask = (const int*)d_in[3];
    // d_in[4] = len_q (fixed 2048 by setup; shapes hardcoded)

    float* out  = (float*)d_out;
    float* attn = out + (size_t)kB * kH * kL * kDV;

    const int smem = (int)sizeof(SmemLayout);
    cudaFuncSetAttribute(fra_kernel, cudaFuncAttributeMaxDynamicSharedMemorySize, smem);

    dim3 grid(kH, kL / TM, kB);   // heads fastest -> mask tiles shared in L2 across 8 heads
    fra_kernel<<<grid, NT, smem>>>(v, a1, a2, mask, out, attn);
}

// round 3
// speedup vs baseline: 1.7066x; 1.7066x over previous
#include <cuda_runtime.h>
#include <cstdint>
#include <cstddef>

namespace {

constexpr int kB  = 4;
constexpr int kH  = 8;
constexpr int kL  = 2048;
constexpr int kR  = 8;
constexpr int kDV = 128;

constexpr int TM = 128;          // rows per CTA
constexpr int KT = 32;           // K-tile (cols per stage)
constexpr int NT = 256;          // threads per CTA
constexpr int NTILES = kL / KT;  // 64

constexpr int PSTRIDE = 36;      // p-tile row stride (floats): banks 4i+q -> conflict-free A frags
constexpr int VSTRIDE = 136;     // v-tile row stride (floats): banks 8q+i -> conflict-free B frags

typedef unsigned long long ull;

// ---------------- packed f32x2 helpers ----------------
__device__ __forceinline__ ull dup2(float x) {
    ull r; asm("mov.b64 %0, {%1,%1};" : "=l"(r) : "f"(x)); return r;
}
__device__ __forceinline__ void unpack2(ull v, float& lo, float& hi) {
    asm("mov.b64 {%0,%1}, %2;" : "=f"(lo), "=f"(hi) : "l"(v));
}
__device__ __forceinline__ ull fma2(ull a, ull b, ull c) {
    ull d; asm("fma.rn.f32x2 %0, %1, %2, %3;" : "=l"(d) : "l"(a), "l"(b), "l"(c));
    return d;
}

// ---------------- tf32 helpers (baseline sm_80+ PTX, no 'a' features) ----------------
__device__ __forceinline__ uint32_t f2tf32(float x) {
    uint32_t r; asm("cvt.rna.tf32.f32 %0, %1;" : "=r"(r) : "f"(x)); return r;
}

__device__ __forceinline__ void mma_tf32(float d[4], const uint32_t a[4],
                                         uint32_t b0, uint32_t b1) {
    asm volatile(
        "mma.sync.aligned.m16n8k8.row.col.f32.tf32.tf32.f32 "
        "{%0,%1,%2,%3}, {%4,%5,%6,%7}, {%8,%9}, {%0,%1,%2,%3};"
        : "+f"(d[0]), "+f"(d[1]), "+f"(d[2]), "+f"(d[3])
        : "r"(a[0]), "r"(a[1]), "r"(a[2]), "r"(a[3]), "r"(b0), "r"(b1));
}

struct __align__(16) SmemLayout {
    float    a2[kR][kL];        // 64 KB
    float    a1t[kR][TM];       // 4 KB
    float    inv[TM];           // 512 B
    uint32_t p[TM][PSTRIDE];    // 18 KB  (tf32 bits, A tile)
    uint32_t v[KT][VSTRIDE];    // 17 KB  (tf32 bits, B tile)
};
// ~106 KB

__global__ void __launch_bounds__(NT, 1)
fra_kernel(const float* __restrict__ gv,
           const float* __restrict__ ga1,
           const float* __restrict__ ga2,
           const int*   __restrict__ gmask,
           float* __restrict__ gout,
           float* __restrict__ gattn)
{
    extern __shared__ char smem_raw[];
    SmemLayout& S = *reinterpret_cast<SmemLayout*>(smem_raw);

    const int h    = blockIdx.x;   // heads fastest: 8 heads share mask tile in L2
    const int tile = blockIdx.y;
    const int b    = blockIdx.z;
    const int bh   = b * kH + h;
    const int i0g  = tile * TM;
    const int t    = threadIdx.x;
    const int w    = t >> 5;
    const int l    = t & 31;

    const float* a2base = ga2 + (size_t)bh * kR * kL;
    const float* a1base = ga1 + ((size_t)bh * kL + i0g) * kR;
    const float* vbase  = gv  + (size_t)bh * kL * kDV;
    const int*   mbase  = gmask + ((size_t)b * kL + i0g) * kL;
    float* attnbase = gattn + ((size_t)bh * kL + i0g) * kL;
    float* outbase  = gout  + ((size_t)bh * kL + i0g) * kDV;

    // ---- load a2 slab + a1 tile (transposed) ----
    {
        const float4* src = (const float4*)a2base;
        float4* dst = (float4*)&S.a2[0][0];
        #pragma unroll
        for (int k = 0; k < (kR * kL / 4) / NT; ++k)
            dst[t + k * NT] = src[t + k * NT];
    }
    if (t < TM) {
        const float4* src = (const float4*)(a1base + (size_t)t * kR);
        float4 q0 = src[0], q1 = src[1];
        S.a1t[0][t] = q0.x; S.a1t[1][t] = q0.y;
        S.a1t[2][t] = q0.z; S.a1t[3][t] = q0.w;
        S.a1t[4][t] = q1.x; S.a1t[5][t] = q1.y;
        S.a1t[6][t] = q1.z; S.a1t[7][t] = q1.w;
    }
    __syncthreads();

    // ================= Phase 1: rowsum of exp(masked scores) =================
    {
        const int i = t >> 1;
        const int jstart = (t & 1) * (kL / 2);
        ull a1d[kR];
        #pragma unroll
        for (int r = 0; r < kR; ++r) a1d[r] = dup2(S.a1t[r][i]);

        const int* mrow = mbase + (size_t)i * kL + jstart;
        const float* a2r0 = &S.a2[0][jstart];

        float s0 = 0.f, s1 = 0.f, s2 = 0.f, s3 = 0.f;
        #pragma unroll 4
        for (int j = 0; j < kL / 2; j += 4) {
            int4 m = *(const int4*)(mrow + j);
            ull a01 = 0ULL, a23 = 0ULL;
            #pragma unroll
            for (int r = 0; r < kR; ++r) {
                ulonglong2 q = *(const ulonglong2*)(a2r0 + (size_t)r * kL + j);
                a01 = fma2(a1d[r], q.x, a01);
                a23 = fma2(a1d[r], q.y, a23);
            }
            float e0, e1, e2, e3;
            unpack2(a01, e0, e1);
            unpack2(a23, e2, e3);
            s0 += __expf(e0) * (float)m.x;
            s1 += __expf(e1) * (float)m.y;
            s2 += __expf(e2) * (float)m.z;
            s3 += __expf(e3) * (float)m.w;
        }
        float sum = (s0 + s1) + (s2 + s3);
        sum += __shfl_xor_sync(0xffffffffu, sum, 1);
        if ((t & 1) == 0) S.inv[i] = 1.0f / sum;
    }
    __syncthreads();

    // ================= Phase 2: probs (fp32-exact attn) + HMMA tf32 PV GEMM =================
    // score mapping: rows 4*rg .. 4*rg+3, cols (within K-tile) 4*cg .. 4*cg+3
    const int rg = t >> 3;
    const int cg = t & 7;
    // GEMM warp tile: rows 32*wm, cols 64*wn; lane -> (groupID, threadInGroup)
    const int wm  = w >> 1;
    const int wn  = w & 1;
    const int qid = l >> 2;
    const int tig = l & 3;

    float a1r[4][kR], invr[4];
    #pragma unroll
    for (int i = 0; i < 4; ++i) {
        #pragma unroll
        for (int r = 0; r < kR; ++r) a1r[i][r] = S.a1t[r][rg * 4 + i];
        invr[i] = S.inv[rg * 4 + i];
    }

    float acc[2][8][4];
    #pragma unroll
    for (int mt = 0; mt < 2; ++mt)
        #pragma unroll
        for (int nt = 0; nt < 8; ++nt)
            #pragma unroll
            for (int e = 0; e < 4; ++e) acc[mt][nt][e] = 0.f;

    for (int jt = 0; jt < NTILES; ++jt) {
        const int j0 = jt * KT;

        // ---- stage v tile -> tf32 smem (row = w + 8k, d = 4l: coalesced + conflict-free) ----
        #pragma unroll
        for (int k = 0; k < 4; ++k) {
            const int row = w + 8 * k;
            float4 q = *(const float4*)(vbase + (size_t)(j0 + row) * kDV + 4 * l);
            uint4 u;
            u.x = f2tf32(q.x); u.y = f2tf32(q.y);
            u.z = f2tf32(q.z); u.w = f2tf32(q.w);
            *(uint4*)&S.v[row][4 * l] = u;
        }

        // ---- scores for 4 rows x 4 cols, exp, normalize, mask; attn STG + p STS ----
        {
            ull sac[4][2];
            #pragma unroll
            for (int i = 0; i < 4; ++i) { sac[i][0] = 0ULL; sac[i][1] = 0ULL; }
            #pragma unroll
            for (int r = 0; r < kR; ++r) {
                ulonglong2 q = *(const ulonglong2*)&S.a2[r][j0 + cg * 4];
                #pragma unroll
                for (int i = 0; i < 4; ++i) {
                    ull ad = dup2(a1r[i][r]);
                    sac[i][0] = fma2(ad, q.x, sac[i][0]);
                    sac[i][1] = fma2(ad, q.y, sac[i][1]);
                }
            }
            #pragma unroll
            for (int i = 0; i < 4; ++i) {
                const int row = rg * 4 + i;
                int4 m = *(const int4*)(mbase + (size_t)row * kL + j0 + cg * 4);
                float e0, e1, e2, e3;
                unpack2(sac[i][0], e0, e1);
                unpack2(sac[i][1], e2, e3);
                float4 p;
                p.x = m.x ? __expf(e0) * invr[i] : 0.f;
                p.y = m.y ? __expf(e1) * invr[i] : 0.f;
                p.z = m.z ? __expf(e2) * invr[i] : 0.f;
                p.w = m.w ? __expf(e3) * invr[i] : 0.f;
                *(float4*)(attnbase + (size_t)row * kL + j0 + cg * 4) = p;
                uint4 u;
                u.x = f2tf32(p.x); u.y = f2tf32(p.y);
                u.z = f2tf32(p.z); u.w = f2tf32(p.w);
                *(uint4*)&S.p[row][cg * 4] = u;
            }
        }

        __syncthreads();

        // ---- HMMA: D[32wm.., 64wn..] += P * V ----
        #pragma unroll
        for (int s = 0; s < 4; ++s) {
            const int k0 = 8 * s + tig;
            uint32_t a[2][4];
            #pragma unroll
            for (int mt = 0; mt < 2; ++mt) {
                const uint32_t* pr = &S.p[32 * wm + 16 * mt][0];
                a[mt][0] = pr[(size_t)qid * PSTRIDE + k0];
                a[mt][1] = pr[(size_t)(qid + 8) * PSTRIDE + k0];
                a[mt][2] = pr[(size_t)qid * PSTRIDE + k0 + 4];
                a[mt][3] = pr[(size_t)(qid + 8) * PSTRIDE + k0 + 4];
            }
            #pragma unroll
            for (int nt = 0; nt < 8; ++nt) {
                const int n = 64 * wn + 8 * nt + qid;
                uint32_t b0 = S.v[8 * s + tig][n];
                uint32_t b1 = S.v[8 * s + 4 + tig][n];
                mma_tf32(acc[0][nt], a[0], b0, b1);
                mma_tf32(acc[1][nt], a[1], b0, b1);
            }
        }

        __syncthreads();
    }

    // ---- epilogue: D fragments -> gout ----
    #pragma unroll
    for (int mt = 0; mt < 2; ++mt) {
        #pragma unroll
        for (int nt = 0; nt < 8; ++nt) {
            const int row = 32 * wm + 16 * mt + qid;
            const int col = 64 * wn + 8 * nt + 2 * tig;
            float2 lo; lo.x = acc[mt][nt][0]; lo.y = acc[mt][nt][1];
            float2 hi; hi.x = acc[mt][nt][2]; hi.y = acc[mt][nt][3];
            *(float2*)(outbase + (size_t)row * kDV + col)       = lo;
            *(float2*)(outbase + (size_t)(row + 8) * kDV + col) = hi;
        }
    }
}

} // namespace

extern "C" void kernel_launch(void* const* d_in, const int* in_sizes, int n_in,
                              void* d_out, int out_size) {
    const float* v    = (const float*)d_in[0];
    const float* a1   = (const float*)d_in[1];
    const float* a2   = (const float*)d_in[2];
    const int*   mask = (const int*)d_in[3];

    float* out  = (float*)d_out;
    float* attn = out + (size_t)kB * kH * kL * kDV;

    const int smem = (int)sizeof(SmemLayout);
    cudaFuncSetAttribute(fra_kernel, cudaFuncAttributeMaxDynamicSharedMemorySize, smem);

    dim3 grid(kH, kL / TM, kB);   // heads fastest -> mask tile L2 reuse across 8 heads
    fra_kernel<<<grid, NT, smem>>>(v, a1, a2, mask, out, attn);
}